// round 1
// baseline (speedup 1.0000x reference)
#include <cuda_runtime.h>

// Problem constants (from reference setup_inputs)
#define NB 8
#define NC 64
#define HH 128
#define WW 128
#define EH 64
#define EW 64
#define THETA 10.0f

#define TROWS 4                 // output rows per block
#define TBLK 256                // threads per block
#define EROWS (TROWS + 2)       // halo rows
#define ECOLS (WW + 2)          // halo cols
#define SSTRIDE 132             // shared row stride (padded)

__global__ __launch_bounds__(TBLK)
void geg_kernel(const float* __restrict__ mask,
                const float* __restrict__ edge,
                float* __restrict__ out)
{
    __shared__ float e_sh[EROWS][SSTRIDE];
    __shared__ float m_sh[EROWS][SSTRIDE];

    const int bid = blockIdx.x;
    const int n   = bid / (HH / TROWS);
    const int ty  = bid % (HH / TROWS);
    const int y0  = ty * TROWS;
    const int t   = threadIdx.x;

    // ---------------- Phase A: bilinear-upsampled edge halo tile ----------
    // e_up(y,x) for y in [y0-1, y0+TROWS], x in [-1, WW]; zero outside image
    // (reference zero-pads AFTER upsampling).
    {
        const float* eptr = edge + (size_t)n * (EH * EW);
        const float sc = 63.0f / 127.0f;   // (EH-1)/(HH-1), align_corners
        for (int idx = t; idx < EROWS * ECOLS; idx += TBLK) {
            int r  = idx / ECOLS;
            int cc = idx % ECOLS;
            int gy = y0 - 1 + r;
            int gx = cc - 1;
            float v = 0.0f;
            if (gy >= 0 && gy < HH && gx >= 0 && gx < WW) {
                float ys = (float)gy * sc;
                float xs = (float)gx * sc;
                int yi = (int)ys;          // gy >= 0 -> trunc == floor
                int xi = (int)xs;
                float wy = ys - (float)yi;
                float wx = xs - (float)xi;
                int y1 = min(yi + 1, EH - 1);
                int x1 = min(xi + 1, EW - 1);
                float a  = eptr[yi * EW + xi];
                float b  = eptr[yi * EW + x1];
                float c0 = eptr[y1 * EW + xi];
                float d  = eptr[y1 * EW + x1];
                float top = a  + (b - a)  * wx;
                float bot = c0 + (d - c0) * wx;
                v = top + (bot - top) * wy;
            }
            e_sh[r][cc] = v;
        }
    }
    __syncthreads();

    // ---------------- Phase B: per-pixel softmax weights (2 px / thread) --
    const int lx  = t % WW;        // x within row (0..127)
    const int lp  = t / WW;        // which vertical pixel pair (0..1)
    const int lr0 = lp * 2;        // tile-local row of first pixel

    float w0[9], w1[9];
    {
        float ev[4][3];
        #pragma unroll
        for (int r = 0; r < 4; r++)
            #pragma unroll
            for (int c2 = 0; c2 < 3; c2++)
                ev[r][c2] = e_sh[lr0 + r][lx + c2];

        const float ec0 = ev[1][1];
        const float ec1 = ev[2][1];
        float s0 = 0.0f, s1 = 0.0f;
        #pragma unroll
        for (int k = 0; k < 9; k++) {
            const int di = k / 3, dj = k % 3;
            float d0 = ec0 - ev[di][dj];
            float d1 = ec1 - ev[di + 1][dj];
            float p0 = __expf(-THETA * d0 * d0);
            float p1 = __expf(-THETA * d1 * d1);
            w0[k] = p0; s0 += p0;
            w1[k] = p1; s1 += p1;
        }
        const float r0 = 1.0f / s0;
        const float r1 = 1.0f / s1;
        #pragma unroll
        for (int k = 0; k < 9; k++) { w0[k] *= r0; w1[k] *= r1; }
    }
    // No barrier needed here: m_sh is disjoint from e_sh and the first
    // channel iteration syncs before anyone consumes m_sh.

    // ---------------- Phase C: channel loop ------------------------------
    const float* mbase = mask + (size_t)n * NC * HH * WW;
    float*       obase = out  + (size_t)n * NC * HH * WW;
    const int gy_out0 = y0 + lr0;

    for (int c = 0; c < NC; c++) {
        const float* mp = mbase + (size_t)c * (HH * WW);

        // cooperative coalesced halo-tile load (zero pad outside image)
        for (int idx = t; idx < EROWS * ECOLS; idx += TBLK) {
            int r  = idx / ECOLS;
            int cc = idx % ECOLS;
            int gy = y0 - 1 + r;
            int gx = cc - 1;
            float v = 0.0f;
            if (gy >= 0 && gy < HH && gx >= 0 && gx < WW)
                v = mp[gy * WW + gx];
            m_sh[r][cc] = v;
        }
        __syncthreads();

        // 4x3 register patch serves both vertically adjacent pixels
        float mv[4][3];
        #pragma unroll
        for (int r = 0; r < 4; r++)
            #pragma unroll
            for (int c2 = 0; c2 < 3; c2++)
                mv[r][c2] = m_sh[lr0 + r][lx + c2];

        float acc0 = 0.0f, acc1 = 0.0f;
        #pragma unroll
        for (int k = 0; k < 9; k++) {
            const int di = k / 3, dj = k % 3;
            acc0 = fmaf(w0[k], mv[di][dj],     acc0);
            acc1 = fmaf(w1[k], mv[di + 1][dj], acc1);
        }

        float* op = obase + (size_t)c * (HH * WW);
        op[(size_t)gy_out0       * WW + lx] = acc0;
        op[(size_t)(gy_out0 + 1) * WW + lx] = acc1;
        __syncthreads();   // protect m_sh before next channel's fill
    }
}

extern "C" void kernel_launch(void* const* d_in, const int* in_sizes, int n_in,
                              void* d_out, int out_size)
{
    const float* mask = (const float*)d_in[0];
    const float* edge = (const float*)d_in[1];
    // Defensive: identify by size (mask = 8*64*128*128, edge = 8*1*64*64)
    if (n_in >= 2 && in_sizes[0] < in_sizes[1]) {
        const float* tmp = mask; mask = edge; edge = tmp;
    }
    float* out = (float*)d_out;

    const int grid = NB * (HH / TROWS);   // 256 blocks
    geg_kernel<<<grid, TBLK>>>(mask, edge, out);
}

// round 2
// speedup vs baseline: 3.8156x; 3.8156x over previous
#include <cuda_runtime.h>

// Problem constants (from reference setup_inputs)
#define NB 8
#define NC 64
#define HH 128
#define WW 128
#define EH 64
#define EW 64
#define THETA 10.0f

#define CSPB 8                         // channels per block
#define NCGRP (NC / CSPB)              // 8 channel groups
#define ROWS_PER_BLK 8                 // 8 warps -> 8 rows
#define NROWBLK (HH / ROWS_PER_BLK)    // 16

__global__ __launch_bounds__(256, 3)
void geg_kernel(const float* __restrict__ mask,
                const float* __restrict__ edge,
                float* __restrict__ out)
{
    const int t    = threadIdx.x;
    const int warp = t >> 5;
    const int lane = t & 31;

    const int rowblk = blockIdx.x;     // 0..15
    const int cgrp   = blockIdx.y;     // 0..7
    const int n      = blockIdx.z;     // 0..7

    const int y  = rowblk * ROWS_PER_BLK + warp;  // output row, 0..127
    const int x0 = lane * 4;                      // first of 4 pixels

    // ---------------- Phase A: bilinear-upsampled edge, 3 rows x 6 vals ---
    // e_up(y+dy, x0-1 .. x0+4); zero outside the HxW image (reference
    // zero-pads AFTER upsampling). Horizontal neighbors via warp shuffle.
    const float* eptr = edge + (size_t)n * (EH * EW);
    const float sc = 63.0f / 127.0f;   // (EH-1)/(HH-1), align_corners

    float er[3][6];
    #pragma unroll
    for (int r = 0; r < 3; r++) {
        const int gy = y - 1 + r;
        float4 ev = make_float4(0.f, 0.f, 0.f, 0.f);
        if (gy >= 0 && gy < HH) {
            const float ys = (float)gy * sc;
            const int   yi = (int)ys;                  // gy>=0 -> trunc==floor
            const float wy = ys - (float)yi;
            const int   y1 = min(yi + 1, EH - 1);
            const float* r0 = eptr + yi * EW;
            const float* r1 = eptr + y1 * EW;
            float v[4];
            #pragma unroll
            for (int p = 0; p < 4; p++) {
                const int   gx = x0 + p;
                const float xs = (float)gx * sc;
                const int   xi = (int)xs;
                const float wx = xs - (float)xi;
                const int   x1 = min(xi + 1, EW - 1);
                const float a  = r0[xi];
                const float b  = r0[x1];
                const float c0 = r1[xi];
                const float d  = r1[x1];
                const float top = a  + (b  - a ) * wx;
                const float bot = c0 + (d  - c0) * wx;
                v[p] = top + (bot - top) * wy;
            }
            ev = make_float4(v[0], v[1], v[2], v[3]);
        }
        float left  = __shfl_up_sync(0xffffffffu, ev.w, 1);
        float right = __shfl_down_sync(0xffffffffu, ev.x, 1);
        if (lane == 0)  left  = 0.f;   // x = -1  -> pad
        if (lane == 31) right = 0.f;   // x = 128 -> pad
        er[r][0] = left; er[r][1] = ev.x; er[r][2] = ev.y;
        er[r][3] = ev.z; er[r][4] = ev.w; er[r][5] = right;
    }

    // ---------------- Phase B: softmax weights, 4 px x 9 taps -------------
    float w[4][9];
    #pragma unroll
    for (int p = 0; p < 4; p++) {
        const float ec = er[1][p + 1];
        float s = 0.f;
        #pragma unroll
        for (int k = 0; k < 9; k++) {
            const float d  = ec - er[k / 3][p + (k % 3)];
            const float pw = __expf(-THETA * d * d);
            w[p][k] = pw;
            s += pw;
        }
        const float rs = 1.f / s;
        #pragma unroll
        for (int k = 0; k < 9; k++) w[p][k] *= rs;
    }

    // ---------------- Phase C: channel loop (no smem, no barriers) --------
    const size_t img   = (size_t)HH * WW;
    const float* mbase = mask + ((size_t)n * NC + (size_t)cgrp * CSPB) * img;
    float*       obase = out  + ((size_t)n * NC + (size_t)cgrp * CSPB) * img;
    const size_t rowoff = (size_t)y * WW + x0;

    #pragma unroll 2
    for (int c = 0; c < CSPB; c++) {
        const float* mp = mbase + (size_t)c * img;

        float mr[3][6];
        #pragma unroll
        for (int r = 0; r < 3; r++) {
            const int gy = y - 1 + r;
            float4 mv = make_float4(0.f, 0.f, 0.f, 0.f);
            if (gy >= 0 && gy < HH)
                mv = *reinterpret_cast<const float4*>(mp + (size_t)gy * WW + x0);
            float left  = __shfl_up_sync(0xffffffffu, mv.w, 1);
            float right = __shfl_down_sync(0xffffffffu, mv.x, 1);
            if (lane == 0)  left  = 0.f;
            if (lane == 31) right = 0.f;
            mr[r][0] = left; mr[r][1] = mv.x; mr[r][2] = mv.y;
            mr[r][3] = mv.z; mr[r][4] = mv.w; mr[r][5] = right;
        }

        float a[4];
        #pragma unroll
        for (int p = 0; p < 4; p++) {
            float s = 0.f;
            #pragma unroll
            for (int k = 0; k < 9; k++)
                s = fmaf(w[p][k], mr[k / 3][p + (k % 3)], s);
            a[p] = s;
        }

        *reinterpret_cast<float4*>(obase + (size_t)c * img + rowoff) =
            make_float4(a[0], a[1], a[2], a[3]);
    }
}

extern "C" void kernel_launch(void* const* d_in, const int* in_sizes, int n_in,
                              void* d_out, int out_size)
{
    const float* mask = (const float*)d_in[0];
    const float* edge = (const float*)d_in[1];
    if (n_in >= 2 && in_sizes[0] < in_sizes[1]) {   // defensive swap by size
        const float* tmp = mask; mask = edge; edge = tmp;
    }
    float* out = (float*)d_out;

    dim3 grid(NROWBLK, NCGRP, NB);   // 16 x 8 x 8 = 1024 blocks
    geg_kernel<<<grid, 256>>>(mask, edge, out);
}

// round 3
// speedup vs baseline: 4.2150x; 1.1047x over previous
#include <cuda_runtime.h>

// Problem constants (from reference setup_inputs)
#define NB 8
#define NC 64
#define HH 128
#define WW 128
#define EH 64
#define EW 64
#define THETA 10.0f

#define CSPB 16                        // channels per block
#define NCGRP (NC / CSPB)              // 4 channel groups
#define ROWS_PER_BLK 4                 // 4 warps -> 4 rows
#define NROWBLK (HH / ROWS_PER_BLK)    // 32
#define TBLK (ROWS_PER_BLK * 32)       // 128 threads

__global__ __launch_bounds__(TBLK, 6)
void geg_kernel(const float* __restrict__ mask,
                const float* __restrict__ edge,
                float* __restrict__ out)
{
    const int t    = threadIdx.x;
    const int warp = t >> 5;
    const int lane = t & 31;

    const int rowblk = blockIdx.x;     // 0..31
    const int cgrp   = blockIdx.y;     // 0..3
    const int n      = blockIdx.z;     // 0..7

    const int y  = rowblk * ROWS_PER_BLK + warp;  // output row, 0..127
    const int x0 = lane * 4;                      // first of 4 pixels

    // ---------------- Phase A: bilinear-upsampled edge, 3 rows x 6 vals ---
    // e_up(y+dy, x0-1 .. x0+4); zero outside the HxW image (reference
    // zero-pads AFTER upsampling). Horizontal neighbors via warp shuffle.
    const float* eptr = edge + (size_t)n * (EH * EW);
    const float sc = 63.0f / 127.0f;   // (EH-1)/(HH-1), align_corners

    float er[3][6];
    #pragma unroll
    for (int r = 0; r < 3; r++) {
        const int gy = y - 1 + r;
        float4 ev = make_float4(0.f, 0.f, 0.f, 0.f);
        if (gy >= 0 && gy < HH) {
            const float ys = (float)gy * sc;
            const int   yi = (int)ys;                  // gy>=0 -> trunc==floor
            const float wy = ys - (float)yi;
            const int   y1 = min(yi + 1, EH - 1);
            const float* r0 = eptr + yi * EW;
            const float* r1 = eptr + y1 * EW;
            float v[4];
            #pragma unroll
            for (int p = 0; p < 4; p++) {
                const int   gx = x0 + p;
                const float xs = (float)gx * sc;
                const int   xi = (int)xs;
                const float wx = xs - (float)xi;
                const int   x1 = min(xi + 1, EW - 1);
                const float a  = r0[xi];
                const float b  = r0[x1];
                const float c0 = r1[xi];
                const float d  = r1[x1];
                const float top = a  + (b  - a ) * wx;
                const float bot = c0 + (d  - c0) * wx;
                v[p] = top + (bot - top) * wy;
            }
            ev = make_float4(v[0], v[1], v[2], v[3]);
        }
        float left  = __shfl_up_sync(0xffffffffu, ev.w, 1);
        float right = __shfl_down_sync(0xffffffffu, ev.x, 1);
        if (lane == 0)  left  = 0.f;   // x = -1  -> pad
        if (lane == 31) right = 0.f;   // x = 128 -> pad
        er[r][0] = left; er[r][1] = ev.x; er[r][2] = ev.y;
        er[r][3] = ev.z; er[r][4] = ev.w; er[r][5] = right;
    }

    // ---------------- Phase B: softmax weights, 4 px x 9 taps -------------
    float w[4][9];
    #pragma unroll
    for (int p = 0; p < 4; p++) {
        const float ec = er[1][p + 1];
        float s = 0.f;
        #pragma unroll
        for (int k = 0; k < 9; k++) {
            const float d  = ec - er[k / 3][p + (k % 3)];
            const float pw = __expf(-THETA * d * d);
            w[p][k] = pw;
            s += pw;
        }
        const float rs = 1.f / s;
        #pragma unroll
        for (int k = 0; k < 9; k++) w[p][k] *= rs;
    }

    // Fold ALL boundary zero-padding of the mask into the (already
    // normalized) weights: a padded tap contributes m=0 to the numerator,
    // identical to zeroing its weight. The denominator (softmax over e with
    // e-padding) is already correct from phase A/B.
    if (y == 0) {
        #pragma unroll
        for (int p = 0; p < 4; p++) { w[p][0] = 0.f; w[p][1] = 0.f; w[p][2] = 0.f; }
    }
    if (y == HH - 1) {
        #pragma unroll
        for (int p = 0; p < 4; p++) { w[p][6] = 0.f; w[p][7] = 0.f; w[p][8] = 0.f; }
    }
    if (lane == 0)  { w[0][0] = 0.f; w[0][3] = 0.f; w[0][6] = 0.f; }
    if (lane == 31) { w[3][2] = 0.f; w[3][5] = 0.f; w[3][8] = 0.f; }

    // ---------------- Phase C: channel loop (no smem, no barriers) --------
    // Row addresses clamped (OOB rows carry zero weight), loads unconditional.
    const size_t img   = (size_t)HH * WW;
    const float* mp = mask + ((size_t)n * NC + (size_t)cgrp * CSPB) * img;
    float*       op = out  + ((size_t)n * NC + (size_t)cgrp * CSPB) * img;

    const int off0 = max(y - 1, 0)      * WW + x0;
    const int off1 = y                  * WW + x0;
    const int off2 = min(y + 1, HH - 1) * WW + x0;
    const int offs = y * WW + x0;

    #pragma unroll 2
    for (int c = 0; c < CSPB; c++) {
        float4 m0 = *reinterpret_cast<const float4*>(mp + off0);
        float4 m1 = *reinterpret_cast<const float4*>(mp + off1);
        float4 m2 = *reinterpret_cast<const float4*>(mp + off2);

        float mr[3][6];
        {
            float l0 = __shfl_up_sync(0xffffffffu, m0.w, 1);
            float r0 = __shfl_down_sync(0xffffffffu, m0.x, 1);
            float l1 = __shfl_up_sync(0xffffffffu, m1.w, 1);
            float r1 = __shfl_down_sync(0xffffffffu, m1.x, 1);
            float l2 = __shfl_up_sync(0xffffffffu, m2.w, 1);
            float r2 = __shfl_down_sync(0xffffffffu, m2.x, 1);
            mr[0][0]=l0; mr[0][1]=m0.x; mr[0][2]=m0.y; mr[0][3]=m0.z; mr[0][4]=m0.w; mr[0][5]=r0;
            mr[1][0]=l1; mr[1][1]=m1.x; mr[1][2]=m1.y; mr[1][3]=m1.z; mr[1][4]=m1.w; mr[1][5]=r1;
            mr[2][0]=l2; mr[2][1]=m2.x; mr[2][2]=m2.y; mr[2][3]=m2.z; mr[2][4]=m2.w; mr[2][5]=r2;
        }

        float a[4];
        #pragma unroll
        for (int p = 0; p < 4; p++) {
            float s = 0.f;
            #pragma unroll
            for (int k = 0; k < 9; k++)
                s = fmaf(w[p][k], mr[k / 3][p + (k % 3)], s);
            a[p] = s;
        }

        *reinterpret_cast<float4*>(op + offs) = make_float4(a[0], a[1], a[2], a[3]);

        mp += img;
        op += img;
    }
}

extern "C" void kernel_launch(void* const* d_in, const int* in_sizes, int n_in,
                              void* d_out, int out_size)
{
    const float* mask = (const float*)d_in[0];
    const float* edge = (const float*)d_in[1];
    if (n_in >= 2 && in_sizes[0] < in_sizes[1]) {   // defensive swap by size
        const float* tmp = mask; mask = edge; edge = tmp;
    }
    float* out = (float*)d_out;

    dim3 grid(NROWBLK, NCGRP, NB);   // 32 x 4 x 8 = 1024 blocks
    geg_kernel<<<grid, TBLK>>>(mask, edge, out);
}

// round 4
// speedup vs baseline: 4.2871x; 1.0171x over previous
#include <cuda_runtime.h>

// Problem constants (from reference setup_inputs)
#define NB 8
#define NC 64
#define HH 128
#define WW 128
#define EH 64
#define EW 64
#define THETA 10.0f

#define CSPB 8                         // channels per block (apply kernel)
#define NCGRP (NC / CSPB)              // 8 channel groups
#define ROWS_PER_BLK 4                 // 4 warps -> 4 rows
#define NROWBLK (HH / ROWS_PER_BLK)    // 32
#define TBLK (ROWS_PER_BLK * 32)       // 128 threads

// Precomputed normalized weights: [n][y][k][x], k = 0..8 tap index.
// 8*128*9*128 floats = 4.72 MB (static device scratch; no runtime alloc).
__device__ float g_wbuf[NB * HH * 9 * WW];

// ---------------------------------------------------------------------------
// Kernel 1: per-pixel softmax weights from bilinear-upsampled edge.
// One warp per output row; each lane handles 4 pixels. Boundary zero-padding
// of the MASK taps is folded into the stored weights (padded tap * m=0 ==
// zero weight; softmax denominator already includes all 9 exps).
// ---------------------------------------------------------------------------
__global__ __launch_bounds__(TBLK)
void geg_weights_kernel(const float* __restrict__ edge)
{
    const int t    = threadIdx.x;
    const int warp = t >> 5;
    const int lane = t & 31;
    const int y    = blockIdx.x * ROWS_PER_BLK + warp;  // 0..127
    const int n    = blockIdx.y;                        // 0..7
    const int x0   = lane * 4;

    const float* eptr = edge + (size_t)n * (EH * EW);
    const float sc = 63.0f / 127.0f;   // (EH-1)/(HH-1), align_corners

    // e_up(y+dy, x0-1 .. x0+4); zero outside image (reference pads AFTER
    // upsampling). Horizontal neighbors via warp shuffle.
    float er[3][6];
    #pragma unroll
    for (int r = 0; r < 3; r++) {
        const int gy = y - 1 + r;
        float4 ev = make_float4(0.f, 0.f, 0.f, 0.f);
        if (gy >= 0 && gy < HH) {
            const float ys = (float)gy * sc;
            const int   yi = (int)ys;
            const float wy = ys - (float)yi;
            const int   y1 = min(yi + 1, EH - 1);
            const float* r0 = eptr + yi * EW;
            const float* r1 = eptr + y1 * EW;
            float v[4];
            #pragma unroll
            for (int p = 0; p < 4; p++) {
                const int   gx = x0 + p;
                const float xs = (float)gx * sc;
                const int   xi = (int)xs;
                const float wx = xs - (float)xi;
                const int   x1 = min(xi + 1, EW - 1);
                const float a  = r0[xi];
                const float b  = r0[x1];
                const float c0 = r1[xi];
                const float d  = r1[x1];
                const float top = a  + (b  - a ) * wx;
                const float bot = c0 + (d  - c0) * wx;
                v[p] = top + (bot - top) * wy;
            }
            ev = make_float4(v[0], v[1], v[2], v[3]);
        }
        float left  = __shfl_up_sync(0xffffffffu, ev.w, 1);
        float right = __shfl_down_sync(0xffffffffu, ev.x, 1);
        if (lane == 0)  left  = 0.f;
        if (lane == 31) right = 0.f;
        er[r][0] = left; er[r][1] = ev.x; er[r][2] = ev.y;
        er[r][3] = ev.z; er[r][4] = ev.w; er[r][5] = right;
    }

    float w[4][9];
    #pragma unroll
    for (int p = 0; p < 4; p++) {
        const float ec = er[1][p + 1];
        float s = 0.f;
        #pragma unroll
        for (int k = 0; k < 9; k++) {
            const float d  = ec - er[k / 3][p + (k % 3)];
            const float pw = __expf(-THETA * d * d);
            w[p][k] = pw;
            s += pw;
        }
        const float rs = 1.f / s;
        #pragma unroll
        for (int k = 0; k < 9; k++) w[p][k] *= rs;
    }

    // Fold mask zero-padding into the weights.
    if (y == 0) {
        #pragma unroll
        for (int p = 0; p < 4; p++) { w[p][0] = 0.f; w[p][1] = 0.f; w[p][2] = 0.f; }
    }
    if (y == HH - 1) {
        #pragma unroll
        for (int p = 0; p < 4; p++) { w[p][6] = 0.f; w[p][7] = 0.f; w[p][8] = 0.f; }
    }
    if (lane == 0)  { w[0][0] = 0.f; w[0][3] = 0.f; w[0][6] = 0.f; }
    if (lane == 31) { w[3][2] = 0.f; w[3][5] = 0.f; w[3][8] = 0.f; }

    // Store: [n][y][k][x], coalesced float4 per (k).
    float* wb = g_wbuf + ((size_t)(n * HH + y) * 9) * WW + x0;
    #pragma unroll
    for (int k = 0; k < 9; k++)
        *reinterpret_cast<float4*>(wb + (size_t)k * WW) =
            make_float4(w[0][k], w[1][k], w[2][k], w[3][k]);
}

// ---------------------------------------------------------------------------
// Kernel 2: apply weights across channels. One warp per row; lane handles 4
// pixels; CSPB channels per block. No smem, no barriers, no branches in loop.
// ---------------------------------------------------------------------------
__global__ __launch_bounds__(TBLK, 7)
void geg_apply_kernel(const float* __restrict__ mask,
                      float* __restrict__ out)
{
    const int t    = threadIdx.x;
    const int warp = t >> 5;
    const int lane = t & 31;

    const int rowblk = blockIdx.x;     // 0..31
    const int cgrp   = blockIdx.y;     // 0..7
    const int n      = blockIdx.z;     // 0..7

    const int y  = rowblk * ROWS_PER_BLK + warp;
    const int x0 = lane * 4;

    // Load the 36 precomputed weights (9 coalesced float4 loads).
    float w[4][9];
    {
        const float* wb = g_wbuf + ((size_t)(n * HH + y) * 9) * WW + x0;
        #pragma unroll
        for (int k = 0; k < 9; k++) {
            float4 v = *reinterpret_cast<const float4*>(wb + (size_t)k * WW);
            w[0][k] = v.x; w[1][k] = v.y; w[2][k] = v.z; w[3][k] = v.w;
        }
    }

    const size_t img = (size_t)HH * WW;
    const float* mp = mask + ((size_t)n * NC + (size_t)cgrp * CSPB) * img;
    float*       op = out  + ((size_t)n * NC + (size_t)cgrp * CSPB) * img;

    // Clamped row offsets (OOB rows carry zero weight).
    const int off0 = max(y - 1, 0)      * WW + x0;
    const int off1 = y                  * WW + x0;
    const int off2 = min(y + 1, HH - 1) * WW + x0;
    const int offs = y * WW + x0;

    #pragma unroll 1
    for (int c = 0; c < CSPB; c++) {
        float4 m0 = *reinterpret_cast<const float4*>(mp + off0);
        float4 m1 = *reinterpret_cast<const float4*>(mp + off1);
        float4 m2 = *reinterpret_cast<const float4*>(mp + off2);

        float mr[3][6];
        {
            float l0 = __shfl_up_sync(0xffffffffu, m0.w, 1);
            float r0 = __shfl_down_sync(0xffffffffu, m0.x, 1);
            float l1 = __shfl_up_sync(0xffffffffu, m1.w, 1);
            float r1 = __shfl_down_sync(0xffffffffu, m1.x, 1);
            float l2 = __shfl_up_sync(0xffffffffu, m2.w, 1);
            float r2 = __shfl_down_sync(0xffffffffu, m2.x, 1);
            mr[0][0]=l0; mr[0][1]=m0.x; mr[0][2]=m0.y; mr[0][3]=m0.z; mr[0][4]=m0.w; mr[0][5]=r0;
            mr[1][0]=l1; mr[1][1]=m1.x; mr[1][2]=m1.y; mr[1][3]=m1.z; mr[1][4]=m1.w; mr[1][5]=r1;
            mr[2][0]=l2; mr[2][1]=m2.x; mr[2][2]=m2.y; mr[2][3]=m2.z; mr[2][4]=m2.w; mr[2][5]=r2;
        }

        float a[4];
        #pragma unroll
        for (int p = 0; p < 4; p++) {
            float s = 0.f;
            #pragma unroll
            for (int k = 0; k < 9; k++)
                s = fmaf(w[p][k], mr[k / 3][p + (k % 3)], s);
            a[p] = s;
        }

        *reinterpret_cast<float4*>(op + offs) = make_float4(a[0], a[1], a[2], a[3]);

        mp += img;
        op += img;
    }
}

extern "C" void kernel_launch(void* const* d_in, const int* in_sizes, int n_in,
                              void* d_out, int out_size)
{
    const float* mask = (const float*)d_in[0];
    const float* edge = (const float*)d_in[1];
    if (n_in >= 2 && in_sizes[0] < in_sizes[1]) {   // defensive swap by size
        const float* tmp = mask; mask = edge; edge = tmp;
    }
    float* out = (float*)d_out;

    dim3 wgrid(NROWBLK, NB);            // 32 x 8 = 256 blocks
    geg_weights_kernel<<<wgrid, TBLK>>>(edge);

    dim3 agrid(NROWBLK, NCGRP, NB);     // 32 x 8 x 8 = 2048 blocks
    geg_apply_kernel<<<agrid, TBLK>>>(mask, out);
}